// round 3
// baseline (speedup 1.0000x reference)
#include <cuda_runtime.h>
#include <cstdint>

// WeightedBCELoss: out[b,s] = (labels[b,s]==0) ? -log(1-pred) : -weight[b]*log(pred)
// pred [4096,8192] f32, labels [4096,8192] i32, weight [4096] f32.
// R3: one block per row (4096 blocks x 256 thr), 8 float4/thread,
// uniform weight load per block, loads front-batched in groups of 4 (MLP~8),
// non-temporal ld/st to keep L2 clean.

#define BATCH 4096
#define SENT  8192
#define V4_PER_ROW (SENT / 4)   // 2048
#define THREADS 256
#define V4_PER_THREAD (V4_PER_ROW / THREADS)  // 8

__device__ __forceinline__ float bce_term(float p, int l, float w) {
    float a = (l == 0) ? (1.0f - p) : p;
    float s = (l == 0) ? 1.0f : w;
    return -s * __logf(a);
}

__global__ __launch_bounds__(THREADS, 8)
void wbce_kernel(const float4* __restrict__ pred,
                 const int4*   __restrict__ labels,
                 const float*  __restrict__ weight,
                 float4*       __restrict__ out)
{
    const int row = blockIdx.x;
    // uniform per block -> single broadcast load
    const float w = __ldg(&weight[row]);

    const long rowbase = (long)row * V4_PER_ROW + threadIdx.x;

    // Two half-batches of 4 float4 each to bound register pressure.
    #pragma unroll
    for (int half = 0; half < 2; half++) {
        const long b = rowbase + half * (4 * THREADS);

        float4 p0 = __ldcs(&pred[b + 0 * THREADS]);
        float4 p1 = __ldcs(&pred[b + 1 * THREADS]);
        float4 p2 = __ldcs(&pred[b + 2 * THREADS]);
        float4 p3 = __ldcs(&pred[b + 3 * THREADS]);
        int4   l0 = __ldcs(&labels[b + 0 * THREADS]);
        int4   l1 = __ldcs(&labels[b + 1 * THREADS]);
        int4   l2 = __ldcs(&labels[b + 2 * THREADS]);
        int4   l3 = __ldcs(&labels[b + 3 * THREADS]);

        float4 o0, o1, o2, o3;
        o0.x = bce_term(p0.x, l0.x, w); o0.y = bce_term(p0.y, l0.y, w);
        o0.z = bce_term(p0.z, l0.z, w); o0.w = bce_term(p0.w, l0.w, w);
        o1.x = bce_term(p1.x, l1.x, w); o1.y = bce_term(p1.y, l1.y, w);
        o1.z = bce_term(p1.z, l1.z, w); o1.w = bce_term(p1.w, l1.w, w);
        o2.x = bce_term(p2.x, l2.x, w); o2.y = bce_term(p2.y, l2.y, w);
        o2.z = bce_term(p2.z, l2.z, w); o2.w = bce_term(p2.w, l2.w, w);
        o3.x = bce_term(p3.x, l3.x, w); o3.y = bce_term(p3.y, l3.y, w);
        o3.z = bce_term(p3.z, l3.z, w); o3.w = bce_term(p3.w, l3.w, w);

        __stcs(&out[b + 0 * THREADS], o0);
        __stcs(&out[b + 1 * THREADS], o1);
        __stcs(&out[b + 2 * THREADS], o2);
        __stcs(&out[b + 3 * THREADS], o3);
    }
}

extern "C" void kernel_launch(void* const* d_in, const int* in_sizes, int n_in,
                              void* d_out, int out_size)
{
    const float4* pred   = (const float4*)d_in[0];
    const int4*   labels = (const int4*)d_in[1];
    const float*  weight = (const float*)d_in[2];
    float4*       out    = (float4*)d_out;

    wbce_kernel<<<BATCH, THREADS>>>(pred, labels, weight, out);
}

// round 4
// speedup vs baseline: 1.0396x; 1.0396x over previous
#include <cuda_runtime.h>
#include <cstdint>

// WeightedBCELoss: out[b,s] = (labels[b,s]==0) ? -log(1-pred) : -weight[b]*log(pred)
// pred [4096,8192] f32, labels [4096,8192] i32, weight [4096] f32.
// R4 = R2 shape (best measured: MLP_p1=4, 16384 blocks) + uniform per-block
// weight load (block covers 512 aligned float4, fully inside one 2048-f4 row).

#define BATCH 4096
#define SENT  8192
#define V4_PER_ROW (SENT / 4)   // 2048
#define THREADS 256

__device__ __forceinline__ float bce_term(float p, int l, float w) {
    float a = (l == 0) ? (1.0f - p) : p;
    float s = (l == 0) ? 1.0f : w;
    return -s * __logf(a);
}

__global__ __launch_bounds__(THREADS, 8)
void wbce_kernel(const float4* __restrict__ pred,
                 const int4*   __restrict__ labels,
                 const float*  __restrict__ weight,
                 float4*       __restrict__ out)
{
    // Block covers float4 range [blk*512, blk*512+512) — entirely inside one
    // row (512 | 2048). row = blk >> 2. Weight is uniform per block.
    const int   row = blockIdx.x >> 2;
    const float w   = __ldg(&weight[row]);

    const long i0 = (long)blockIdx.x * 512 + threadIdx.x;
    const long i1 = i0 + 256;

    // Front-batched: 4 independent 16B loads (MLP_p1 = 4, the measured sweet spot).
    float4 p0 = __ldcs(&pred[i0]);
    float4 p1 = __ldcs(&pred[i1]);
    int4   l0 = __ldcs(&labels[i0]);
    int4   l1 = __ldcs(&labels[i1]);

    float4 o0, o1;
    o0.x = bce_term(p0.x, l0.x, w);
    o0.y = bce_term(p0.y, l0.y, w);
    o0.z = bce_term(p0.z, l0.z, w);
    o0.w = bce_term(p0.w, l0.w, w);
    o1.x = bce_term(p1.x, l1.x, w);
    o1.y = bce_term(p1.y, l1.y, w);
    o1.z = bce_term(p1.z, l1.z, w);
    o1.w = bce_term(p1.w, l1.w, w);

    __stcs(&out[i0], o0);
    __stcs(&out[i1], o1);
}

extern "C" void kernel_launch(void* const* d_in, const int* in_sizes, int n_in,
                              void* d_out, int out_size)
{
    const float4* pred   = (const float4*)d_in[0];
    const int4*   labels = (const int4*)d_in[1];
    const float*  weight = (const float*)d_in[2];
    float4*       out    = (float4*)d_out;

    const int total_v4 = BATCH * V4_PER_ROW;   // 8,388,608
    wbce_kernel<<<total_v4 / 512, THREADS>>>(pred, labels, weight, out);
}